// round 1
// baseline (speedup 1.0000x reference)
#include <cuda_runtime.h>
#include <cuda_bf16.h>

// Problem constants
#define BATCH 4
#define SEQ   4096
#define DIM   1024

// GEMM tile config
#define BM 128
#define BN 128
#define BK 16
#define SLD 20  // padded smem row stride in floats (conflict-free, 16B-aligned rows)

// Scratch (allocation-free rule: __device__ globals)
__device__ float g_Q [(long long)BATCH*SEQ*DIM];
__device__ float g_K [(long long)BATCH*SEQ*DIM];
__device__ float g_Vt[(long long)BATCH*SEQ*DIM];   // layout [e][b*SEQ + t] (ld = BATCH*SEQ)
__device__ float g_S [(long long)BATCH*SEQ*SEQ];   // scores / probs, 256 MB

__device__ __forceinline__ unsigned f2tf(float f) {
    unsigned u;
    asm("cvt.rna.tf32.f32 %0, %1;" : "=r"(u) : "f"(f));
    return u;
}

__device__ __forceinline__ void cp16(void* sm, const void* gm) {
    unsigned s = (unsigned)__cvta_generic_to_shared(sm);
    asm volatile("cp.async.cg.shared.global [%0], [%1], 16;" :: "r"(s), "l"(gm));
}

// C[M,N] = alpha * A[M,K] * B[N,K]^T   (both operands K-contiguous)
// A: lda, B: ldb, C: ldc. Batch via blockIdx.z with element strides sA/sB/sC.
// TRANS: store C transposed as C[n*ldc + m] (used to produce V^T).
template<bool TRANS>
__global__ void __launch_bounds__(256, 2) gemm_tf32(
    const float* __restrict__ A, const float* __restrict__ B, float* __restrict__ C,
    int lda, int ldb, int ldc,
    long long sA, long long sB, long long sC,
    int K, float alpha)
{
    __shared__ float As[2][BM * SLD];
    __shared__ float Bs[2][BN * SLD];

    const float* Ab = A + (long long)blockIdx.z * sA + (long long)blockIdx.y * BM * lda;
    const float* Bb = B + (long long)blockIdx.z * sB + (long long)blockIdx.x * BN * ldb;
    float*       Cb = C + (long long)blockIdx.z * sC;

    const int tid  = threadIdx.x;
    const int lane = tid & 31;
    const int warp = tid >> 5;
    const int wm = warp >> 2;      // 0..1
    const int wn = warp & 3;       // 0..3
    const int g  = lane >> 2;      // group id 0..7
    const int tg = lane & 3;       // thread-in-group 0..3

    float acc[4][4][4];
    #pragma unroll
    for (int i = 0; i < 4; i++)
        #pragma unroll
        for (int j = 0; j < 4; j++)
            #pragma unroll
            for (int c = 0; c < 4; c++) acc[i][j][c] = 0.f;

    const int KT = K / BK;

    auto load = [&](int kt, int st) {
        #pragma unroll
        for (int i = 0; i < 2; i++) {
            int ch = tid + i * 256;
            int r = ch >> 2, kc = ch & 3;
            cp16(&As[st][r * SLD + kc * 4], Ab + (long long)r * lda + kt * BK + kc * 4);
        }
        #pragma unroll
        for (int i = 0; i < 2; i++) {
            int ch = tid + i * 256;
            int r = ch >> 2, kc = ch & 3;
            cp16(&Bs[st][r * SLD + kc * 4], Bb + (long long)r * ldb + kt * BK + kc * 4);
        }
        asm volatile("cp.async.commit_group;");
    };

    load(0, 0);
    load(1, 1);

    for (int kt = 0; kt < KT; kt++) {
        if (kt + 2 < KT) asm volatile("cp.async.wait_group 1;");
        else             asm volatile("cp.async.wait_group 0;");
        __syncthreads();

        const int st = kt & 1;
        const float* as = As[st];
        const float* bs = Bs[st];

        #pragma unroll
        for (int ks = 0; ks < BK; ks += 8) {
            unsigned af[4][4], bf[4][2];
            #pragma unroll
            for (int mt = 0; mt < 4; mt++) {
                int r0 = wm * 64 + mt * 16;
                af[mt][0] = f2tf(as[(r0 + g    ) * SLD + ks + tg    ]);
                af[mt][1] = f2tf(as[(r0 + g + 8) * SLD + ks + tg    ]);
                af[mt][2] = f2tf(as[(r0 + g    ) * SLD + ks + tg + 4]);
                af[mt][3] = f2tf(as[(r0 + g + 8) * SLD + ks + tg + 4]);
            }
            #pragma unroll
            for (int nt = 0; nt < 4; nt++) {
                int c0 = wn * 32 + nt * 8;
                bf[nt][0] = f2tf(bs[(c0 + g) * SLD + ks + tg    ]);
                bf[nt][1] = f2tf(bs[(c0 + g) * SLD + ks + tg + 4]);
            }
            #pragma unroll
            for (int mt = 0; mt < 4; mt++)
                #pragma unroll
                for (int nt = 0; nt < 4; nt++)
                    asm volatile(
                        "mma.sync.aligned.m16n8k8.row.col.f32.tf32.tf32.f32 "
                        "{%0,%1,%2,%3}, {%4,%5,%6,%7}, {%8,%9}, {%0,%1,%2,%3};"
                        : "+f"(acc[mt][nt][0]), "+f"(acc[mt][nt][1]),
                          "+f"(acc[mt][nt][2]), "+f"(acc[mt][nt][3])
                        : "r"(af[mt][0]), "r"(af[mt][1]), "r"(af[mt][2]), "r"(af[mt][3]),
                          "r"(bf[nt][0]), "r"(bf[nt][1]));
        }
        __syncthreads();
        if (kt + 2 < KT) load(kt + 2, st);
    }

    // Epilogue
    #pragma unroll
    for (int mt = 0; mt < 4; mt++) {
        int row0 = blockIdx.y * BM + wm * 64 + mt * 16 + g;
        #pragma unroll
        for (int nt = 0; nt < 4; nt++) {
            int col0 = blockIdx.x * BN + wn * 32 + nt * 8 + 2 * tg;
            float v0 = acc[mt][nt][0] * alpha;
            float v1 = acc[mt][nt][1] * alpha;
            float v2 = acc[mt][nt][2] * alpha;
            float v3 = acc[mt][nt][3] * alpha;
            if (!TRANS) {
                *(float2*)&Cb[(long long)(row0    ) * ldc + col0] = make_float2(v0, v1);
                *(float2*)&Cb[(long long)(row0 + 8) * ldc + col0] = make_float2(v2, v3);
            } else {
                Cb[(long long)(col0    ) * ldc + row0    ] = v0;
                Cb[(long long)(col0 + 1) * ldc + row0    ] = v1;
                Cb[(long long)(col0    ) * ldc + row0 + 8] = v2;
                Cb[(long long)(col0 + 1) * ldc + row0 + 8] = v3;
            }
        }
    }
}

// Row softmax over SEQ-length rows, one block per row, in place.
__global__ void softmax_kernel(float* __restrict__ S) {
    long long row = blockIdx.x;
    float4* p4 = (float4*)(S + row * SEQ);
    const int tid = threadIdx.x, lane = tid & 31, warp = tid >> 5;
    __shared__ float rmax[8], rsum[8];

    float4 v[4];
    float mx = -1e30f;
    #pragma unroll
    for (int i = 0; i < 4; i++) {
        v[i] = p4[tid + i * 256];
        mx = fmaxf(mx, fmaxf(fmaxf(v[i].x, v[i].y), fmaxf(v[i].z, v[i].w)));
    }
    #pragma unroll
    for (int o = 16; o > 0; o >>= 1) mx = fmaxf(mx, __shfl_xor_sync(0xffffffffu, mx, o));
    if (lane == 0) rmax[warp] = mx;
    __syncthreads();
    float gm = rmax[0];
    #pragma unroll
    for (int j = 1; j < 8; j++) gm = fmaxf(gm, rmax[j]);

    float s = 0.f;
    #pragma unroll
    for (int i = 0; i < 4; i++) {
        v[i].x = __expf(v[i].x - gm);
        v[i].y = __expf(v[i].y - gm);
        v[i].z = __expf(v[i].z - gm);
        v[i].w = __expf(v[i].w - gm);
        s += v[i].x + v[i].y + v[i].z + v[i].w;
    }
    #pragma unroll
    for (int o = 16; o > 0; o >>= 1) s += __shfl_xor_sync(0xffffffffu, s, o);
    if (lane == 0) rsum[warp] = s;
    __syncthreads();
    float gs = 0.f;
    #pragma unroll
    for (int j = 0; j < 8; j++) gs += rsum[j];
    float inv = 1.f / gs;

    #pragma unroll
    for (int i = 0; i < 4; i++) {
        v[i].x *= inv; v[i].y *= inv; v[i].z *= inv; v[i].w *= inv;
        p4[tid + i * 256] = v[i];
    }
}

extern "C" void kernel_launch(void* const* d_in, const int* in_sizes, int n_in,
                              void* d_out, int out_size) {
    const float* x  = (const float*)d_in[0];
    const float* Wq = (const float*)d_in[1];
    const float* Wk = (const float*)d_in[2];
    const float* Wv = (const float*)d_in[3];
    float* out = (float*)d_out;

    float *pQ, *pK, *pVt, *pS;
    cudaGetSymbolAddress((void**)&pQ,  g_Q);
    cudaGetSymbolAddress((void**)&pK,  g_K);
    cudaGetSymbolAddress((void**)&pVt, g_Vt);
    cudaGetSymbolAddress((void**)&pS,  g_S);

    const long long BT = (long long)BATCH * SEQ;            // 16384
    const long long strideQK = (long long)SEQ * DIM;        // per-batch Q/K stride
    const long long strideS  = (long long)SEQ * SEQ;

    // Projections over flattened [B*T, D]
    dim3 gProj(DIM / BN, (unsigned)(BT / BM), 1);
    gemm_tf32<false><<<gProj, 256>>>(x, Wq, pQ,  DIM, DIM, DIM,        0, 0, 0, DIM, 1.0f);
    gemm_tf32<false><<<gProj, 256>>>(x, Wk, pK,  DIM, DIM, DIM,        0, 0, 0, DIM, 1.0f);
    gemm_tf32<true ><<<gProj, 256>>>(x, Wv, pVt, DIM, DIM, (int)BT,    0, 0, 0, DIM, 1.0f);

    // Scores: S_b = (Q_b K_b^T) / sqrt(D)
    dim3 gS(SEQ / BN, SEQ / BM, BATCH);
    gemm_tf32<false><<<gS, 256>>>(pQ, pK, pS, DIM, DIM, SEQ,
                                  strideQK, strideQK, strideS, DIM, 0.03125f);

    // Row softmax, in place
    softmax_kernel<<<(unsigned)BT, 256>>>(pS);

    // Output: O_b = P_b V_b   (V^T layout: element (e, t) at e*BT + b*SEQ + t)
    dim3 gO(DIM / BN, SEQ / BM, BATCH);
    gemm_tf32<false><<<gO, 256>>>(pS, pVt, out, SEQ, (int)BT, DIM,
                                  strideS, (long long)SEQ, (long long)SEQ * DIM,
                                  SEQ, 1.0f);
}